// round 17
// baseline (speedup 1.0000x reference)
#include <cuda_runtime.h>
#include <cuda_bf16.h>
#include <cuda_fp16.h>
#include <cstdint>

// ---------------- problem constants ----------------
#define NTOK    4096
#define CDIM    256
#define NH      8
#define HD      32
#define LK      32
#define GB      16
#define NW      64
#define BW      1024
#define MROWS   65536
#define NKEY    48

typedef unsigned long long u64;
typedef __half fp16;

// ---------------- device-global scratch ----------------
__device__ __align__(16) fp16  g_q[(size_t)BW * NH * NW * HD];
__device__ __align__(16) fp16  g_k[(size_t)BW * NH * NW * HD];
__device__ __align__(16) fp16  g_v[(size_t)BW * NH * NW * HD];
__device__ __align__(16) fp16  g_ao[(size_t)MROWS * CDIM];
__device__ __align__(16) fp16  g_wqkvT[768 * 256];
__device__ __align__(16) fp16  g_wpT[256 * 256];
__device__ __align__(16) fp16  g_ekT[LK * NW];
__device__ __align__(16) fp16  g_evT[LK * NW];

// ---------------- helpers ----------------
__device__ __forceinline__ uint32_t smem_u32(const void* p) {
    uint32_t a;
    asm("{ .reg .u64 t; cvta.to.shared.u64 t, %1; cvt.u32.u64 %0, t; }" : "=r"(a) : "l"(p));
    return a;
}
__device__ __forceinline__ void cp16(uint32_t saddr, const void* gaddr) {
    asm volatile("cp.async.cg.shared.global [%0], [%1], 16;"
                 :: "r"(saddr), "l"(gaddr));
}
#define CP_COMMIT() asm volatile("cp.async.commit_group;" ::: "memory")
#define CP_WAIT(n)  asm volatile("cp.async.wait_group %0;" :: "n"(n) : "memory")

__device__ __forceinline__ void ldsm4(uint32_t (&r)[4], uint32_t addr) {
    asm volatile("ldmatrix.sync.aligned.m8n8.x4.shared.b16 {%0,%1,%2,%3}, [%4];"
                 : "=r"(r[0]), "=r"(r[1]), "=r"(r[2]), "=r"(r[3]) : "r"(addr));
}
__device__ __forceinline__ void ldsm4t(uint32_t (&r)[4], uint32_t addr) {
    asm volatile("ldmatrix.sync.aligned.m8n8.x4.trans.shared.b16 {%0,%1,%2,%3}, [%4];"
                 : "=r"(r[0]), "=r"(r[1]), "=r"(r[2]), "=r"(r[3]) : "r"(addr));
}
__device__ __forceinline__ void mma16816h(float (&d)[4], const uint32_t (&a)[4],
                                          uint32_t b0, uint32_t b1) {
    asm volatile("mma.sync.aligned.m16n8k16.row.col.f32.f16.f16.f32 "
                 "{%0,%1,%2,%3}, {%4,%5,%6,%7}, {%8,%9}, {%0,%1,%2,%3};"
                 : "+f"(d[0]), "+f"(d[1]), "+f"(d[2]), "+f"(d[3])
                 : "r"(a[0]), "r"(a[1]), "r"(a[2]), "r"(a[3]), "r"(b0), "r"(b1));
}
__device__ __forceinline__ uint32_t h2pack(float x, float y) {
    __half2 h = __floats2half2_rn(x, y);
    return *(uint32_t*)&h;
}

// =================================================================================
// conv_w: W_qkv/W_proj -> [n][k] fp16 transposed, plus E_k/E_v -> E^T fp16.
// =================================================================================
__global__ void __launch_bounds__(64) conv_w(const float* __restrict__ Wqkv,
                                             const float* __restrict__ Wp,
                                             const float* __restrict__ Ek,
                                             const float* __restrict__ Ev)
{
    const int blk = blockIdx.x;
    if (blk < 1024) {
        const int n = blk;
        for (int k = threadIdx.x; k < CDIM; k += 64) {
            if (n < 768)
                g_wqkvT[(size_t)n * CDIM + k] = __float2half_rn(Wqkv[(size_t)k * 768 + n]);
            else
                g_wpT[(size_t)(n - 768) * CDIM + k] = __float2half_rn(Wp[(size_t)k * CDIM + (n - 768)]);
        }
    } else {
        const int base = (blk - 1024) * 128 + threadIdx.x * 2;
        #pragma unroll
        for (int u = 0; u < 2; u++) {
            const int t = base + u;
            const int l = t >> 6, n = t & 63;
            g_ekT[t] = __float2half_rn(Ek[n * LK + l]);
            g_evT[t] = __float2half_rn(Ev[n * LK + l]);
        }
    }
}

// =================================================================================
// HMMA fp16 GEMM (as R16): 1 mma/tile, one sync per k-iter.
//   MODE 0: qkv — A direct from fp32 x (window gather) LDG+cvt+STS.
//   MODE 1: proj — A = g_ao via cp.async; window-reverse fp32 out + bias.
// =================================================================================
#define RS   80
#define AA   0
#define BB   10240
#define STG  20480
#define SMEMB (2 * STG)

template<int MODE>
__global__ void __launch_bounds__(256) hmma_gemm(const float* __restrict__ xin,
                                                 const float* __restrict__ bias,
                                                 float* __restrict__ outp)
{
    extern __shared__ char sm[];
    const uint32_t smb = smem_u32(sm);
    const int tid  = threadIdx.x;
    const int lane = tid & 31, wid = tid >> 5;
    const int warp_m = wid >> 2, warp_n = wid & 3;      // 2m x 4n
    const int bx = blockIdx.y;
    const int by = blockIdx.x;

    const fp16* B_g = (MODE == 0) ? g_wqkvT : g_wpT;
    const size_t b_base = (size_t)(by * 128) * CDIM;

    const float* xrow[2];
    const fp16*  arow[2];
    #pragma unroll
    for (int c = 0; c < 2; c++) {
        const int idx = tid + c * 256;
        const int row = idx >> 2;
        const int kc  = idx & 3;
        if (MODE == 0) {
            const int r_in = bx * 128 + row;
            const int w_in = r_in >> 6, t_in = r_in & 63;
            const int b    = w_in >> 6, wrem = w_in & 63;
            const int gtok = (((wrem >> 3) * 8 + (t_in >> 3)) << 6)
                           + ((wrem & 7) * 8 + (t_in & 7));
            xrow[c] = xin + ((size_t)(b * NTOK + gtok)) * CDIM + kc * 8;
        } else {
            arow[c] = g_ao + (size_t)(bx * 128 + row) * CDIM + kc * 8;
        }
    }

    uint32_t areg[2][4];
    auto ldgA = [&](int kt) {
        #pragma unroll
        for (int c = 0; c < 2; c++) {
            float4 v0 = *(const float4*)(xrow[c] + kt * 32);
            float4 v1 = *(const float4*)(xrow[c] + kt * 32 + 4);
            areg[c][0] = h2pack(v0.x, v0.y);
            areg[c][1] = h2pack(v0.z, v0.w);
            areg[c][2] = h2pack(v1.x, v1.y);
            areg[c][3] = h2pack(v1.z, v1.w);
        }
    };
    auto stsA = [&](int s) {
        #pragma unroll
        for (int c = 0; c < 2; c++) {
            const int idx = tid + c * 256;
            const int row = idx >> 2, kc = idx & 3;
            *(uint4*)(sm + s * STG + AA + row * RS + kc * 16) = *(uint4*)areg[c];
        }
    };
    auto loadB = [&](int s, int kt) {
        #pragma unroll
        for (int c = 0; c < 2; c++) {
            const int idx = tid + c * 256;
            const int row = idx >> 2, kc = idx & 3;
            cp16(smb + s * STG + BB + row * RS + kc * 16,
                 B_g + b_base + (size_t)row * CDIM + (size_t)kt * 32 + kc * 8);
        }
    };
    auto loadA_cp = [&](int s, int kt) {
        #pragma unroll
        for (int c = 0; c < 2; c++) {
            const int idx = tid + c * 256;
            const int row = idx >> 2, kc = idx & 3;
            cp16(smb + s * STG + AA + row * RS + kc * 16,
                 arow[c] + (size_t)kt * 32);
        }
    };

    const uint32_t a_frag = (uint32_t)((warp_m * 64 + (lane & 15)) * RS
                                       + (lane >> 4) * 16);
    const uint32_t b_frag = (uint32_t)((warp_n * 32 + (lane & 7) + ((lane >> 4) << 3)) * RS
                                       + ((lane >> 3) & 1) * 16);

    float acc[4][4][4] = {};

    if (MODE == 0) ldgA(0);
    else           loadA_cp(0, 0);
    loadB(0, 0);
    CP_COMMIT();

    #pragma unroll 1
    for (int it = 0; it < 8; it++) {
        CP_WAIT(0);
        if (MODE == 0) stsA(it & 1);
        __syncthreads();
        if (it < 7) {
            if (MODE == 0) ldgA(it + 1);
            else           loadA_cp((it + 1) & 1, it + 1);
            loadB((it + 1) & 1, it + 1);
            CP_COMMIT();
        }

        const uint32_t st = smb + (it & 1) * STG;
        #pragma unroll
        for (int kk = 0; kk < 2; kk++) {
            uint32_t aa[4][4], bb[4][2];
            #pragma unroll
            for (int mt = 0; mt < 4; mt++)
                ldsm4(aa[mt], st + AA + a_frag + mt * (16 * RS) + kk * 32);
            #pragma unroll
            for (int np = 0; np < 2; np++) {
                uint32_t tb[4];
                ldsm4(tb, st + BB + b_frag + np * (16 * RS) + kk * 32);
                bb[np * 2][0] = tb[0]; bb[np * 2][1] = tb[1];
                bb[np * 2 + 1][0] = tb[2]; bb[np * 2 + 1][1] = tb[3];
            }
            #pragma unroll
            for (int mt = 0; mt < 4; mt++)
                #pragma unroll
                for (int nt = 0; nt < 4; nt++)
                    mma16816h(acc[mt][nt], aa[mt], bb[nt][0], bb[nt][1]);
        }
    }

    // ---------------- epilogue ----------------
    const int w = bx * 2 + warp_m;
    const int qrow = lane >> 2;
    const int qcol = (lane & 3) * 2;

    if (MODE == 0) {
        const int s  = by >> 1;
        fp16* dst = (s == 0) ? g_q : ((s == 1) ? g_k : g_v);
        const float qs = (s == 0) ? 0.17677669529663687f : 1.0f;
        const int h = (by & 1) * 4 + warp_n;
        const size_t hb = ((size_t)(w * NH + h)) << 11;
        #pragma unroll
        for (int nt = 0; nt < 4; nt++) {
            const int d  = nt * 8 + qcol;
            const int jg = by * 128 + warp_n * 32 + d;
            const float2 b2 = *(const float2*)(bias + jg);
            #pragma unroll
            for (int mt = 0; mt < 4; mt++) {
                const int tok = mt * 16 + qrow;
                *(uint32_t*)(dst + hb + ((size_t)tok << 5) + d) =
                    h2pack((acc[mt][nt][0] + b2.x) * qs, (acc[mt][nt][1] + b2.y) * qs);
                *(uint32_t*)(dst + hb + ((size_t)(tok + 8) << 5) + d) =
                    h2pack((acc[mt][nt][2] + b2.x) * qs, (acc[mt][nt][3] + b2.y) * qs);
            }
        }
    } else {
        const int b = w >> 6, wrem = w & 63;
        #pragma unroll
        for (int nt = 0; nt < 4; nt++) {
            const int jg = by * 128 + warp_n * 32 + nt * 8 + qcol;
            const float2 b2 = *(const float2*)(bias + jg);
            #pragma unroll
            for (int mt = 0; mt < 4; mt++) {
                #pragma unroll
                for (int half = 0; half < 2; half++) {
                    const int tok = mt * 16 + qrow + half * 8;
                    const int gtok = (((wrem >> 3) * 8 + (tok >> 3)) << 6)
                                   + ((wrem & 7) * 8 + (tok & 7));
                    float2 o = make_float2(acc[mt][nt][half * 2]     + b2.x,
                                           acc[mt][nt][half * 2 + 1] + b2.y);
                    *(float2*)(outp + ((size_t)(b * NTOK + gtok)) * CDIM + jg) = o;
                }
            }
        }
    }
}

// =================================================================================
// HMMA attention, fp16, with register prefetch of V and Q tiles to hide DRAM
// latency behind K/V compression mma work.
// =================================================================================
#define ET_SZ   4608
#define ARS     80
#define W_STG   0
#define W_KC    5120
#define W_VC    8960
#define W_SZ    12800
#define ATTN_SM (2 * ET_SZ + 2 * W_SZ)   // 34816

__global__ void __launch_bounds__(64) attn_kernel(const float* __restrict__ k_bank,
                                                  const float* __restrict__ v_bank)
{
    extern __shared__ char sm[];
    const uint32_t smb = smem_u32(sm);
    const int tid  = threadIdx.x;
    const int lane = tid & 31, wid = tid >> 5;
    const int blk  = blockIdx.x;
    const int w    = blk >> 2;
    const int h    = (blk & 3) * 2 + wid;

    const size_t qkvoff = ((size_t)(w * NH + h)) << 11;

    // ---- prefetch V and Q tiles into registers (in flight during K phase)
    uint4 vreg[8], qreg[8];
    #pragma unroll
    for (int i = 0; i < 8; i++) {
        const int idx = lane + i * 32;
        vreg[i] = *(const uint4*)(g_v + qkvoff + idx * 8);
        qreg[i] = *(const uint4*)(g_q + qkvoff + idx * 8);
    }

    // ---- stage E^T matrices (block cooperative)
    {
        const fp16* srcs[2] = { g_ekT, g_evT };
        #pragma unroll
        for (int i = 0; i < 8; i++) {
            const int idx = tid + i * 64;
            const int mat = idx >> 8;
            const int r   = (idx & 255) >> 3;
            const int c   = idx & 7;
            *(uint4*)(sm + mat * ET_SZ + r * 144 + c * 16) =
                *(const uint4*)(srcs[mat] + r * 64 + c * 8);
        }
    }
    __syncthreads();

    char* wbp = sm + 2 * ET_SZ + wid * W_SZ;
    const uint32_t wbu = smb + 2 * ET_SZ + wid * W_SZ;
    const uint32_t stg = wbu + W_STG;
    const uint32_t kc  = wbu + W_KC;
    const uint32_t vc  = wbu + W_VC;

    const int r  = lane >> 2;
    const int c2 = (lane & 3) * 2;

    // ---- bank row writer (rows 32..47 of a compressed buffer)
    auto bank_rows = [&](const float* bank, char* ccp) {
        const int g  = lane >> 1;
        const int d0 = (lane & 1) * 16;
        float bv[16];
        #pragma unroll
        for (int i = 0; i < 4; i++)
            *(float4*)(bv + i * 4) =
                *(const float4*)(bank + g * CDIM + h * HD + d0 + i * 4);
        #pragma unroll
        for (int i = 0; i < 8; i++)
            *(uint32_t*)(ccp + (32 + g) * ARS + (d0 + 2 * i) * 2) =
                h2pack(bv[2 * i], bv[2 * i + 1]);
    };

    // ---- compression: Kc/Vc[0..31] = E^T @ tile (M=32 N=32 K=64)
    auto compress = [&](uint32_t eT, char* ccp) {
        float acc[2][4][4] = {};
        #pragma unroll
        for (int kt = 0; kt < 4; kt++) {
            uint32_t A[2][4], B[2][4];
            #pragma unroll
            for (int mt = 0; mt < 2; mt++) {
                const uint32_t ao = (uint32_t)((mt * 16 + (lane & 15)) * 144
                                               + kt * 32 + (lane >> 4) * 16);
                ldsm4(A[mt], eT + ao);
            }
            const uint32_t to = (uint32_t)((kt * 16 + (lane & 7) + ((lane >> 3) & 1) * 8) * ARS
                                           + (lane >> 4) * 16);
            #pragma unroll
            for (int dg = 0; dg < 2; dg++)
                ldsm4t(B[dg], stg + to + dg * 32);
            #pragma unroll
            for (int mt = 0; mt < 2; mt++)
                #pragma unroll
                for (int dg = 0; dg < 2; dg++) {
                    mma16816h(acc[mt][dg * 2],     A[mt], B[dg][0], B[dg][1]);
                    mma16816h(acc[mt][dg * 2 + 1], A[mt], B[dg][2], B[dg][3]);
                }
        }
        #pragma unroll
        for (int mt = 0; mt < 2; mt++)
            #pragma unroll
            for (int nt = 0; nt < 4; nt++) {
                const int d = nt * 8 + c2;
                *(uint32_t*)(ccp + (mt * 16 + r) * ARS + d * 2) =
                    h2pack(acc[mt][nt][0], acc[mt][nt][1]);
                *(uint32_t*)(ccp + (mt * 16 + r + 8) * ARS + d * 2) =
                    h2pack(acc[mt][nt][2], acc[mt][nt][3]);
            }
    };

    // ================= phase K =================
    #pragma unroll
    for (int i = 0; i < 8; i++) {
        const int idx = lane + i * 32;
        const int rr = idx >> 2, cc = idx & 3;
        *(uint4*)(wbp + W_STG + rr * ARS + cc * 16) =
            *(const uint4*)(g_k + qkvoff + idx * 8);
    }
    bank_rows(k_bank, wbp + W_KC);
    __syncwarp();
    compress(smb, wbp + W_KC);
    __syncwarp();

    // ================= phase V (tile already in registers) =================
    #pragma unroll
    for (int i = 0; i < 8; i++) {
        const int idx = lane + i * 32;
        const int rr = idx >> 2, cc = idx & 3;
        *(uint4*)(wbp + W_STG + rr * ARS + cc * 16) = vreg[i];
    }
    bank_rows(v_bank, wbp + W_VC);
    __syncwarp();
    compress(smb + ET_SZ, wbp + W_VC);
    __syncwarp();

    // ================= phase Q (tile already in registers) =================
    #pragma unroll
    for (int i = 0; i < 8; i++) {
        const int idx = lane + i * 32;
        const int rr = idx >> 2, cc = idx & 3;
        *(uint4*)(wbp + W_STG + rr * ARS + cc * 16) = qreg[i];
    }
    __syncwarp();

    // ================= QK: M=64 N=48 K=32 =================
    float S[4][6][4] = {};
    #pragma unroll
    for (int kd = 0; kd < 2; kd++) {
        uint32_t Q[4][4], K[3][4];
        #pragma unroll
        for (int mt = 0; mt < 4; mt++) {
            const uint32_t ao = (uint32_t)((mt * 16 + (lane & 15)) * ARS
                                           + kd * 32 + (lane >> 4) * 16);
            ldsm4(Q[mt], stg + ao);
        }
        const uint32_t bo = (uint32_t)(((lane & 7) + ((lane >> 4) << 3)) * ARS
                                       + ((lane >> 3) & 1) * 16 + kd * 32);
        #pragma unroll
        for (int jg = 0; jg < 3; jg++)
            ldsm4(K[jg], kc + jg * (16 * ARS) + bo);
        #pragma unroll
        for (int mt = 0; mt < 4; mt++)
            #pragma unroll
            for (int jg = 0; jg < 3; jg++) {
                mma16816h(S[mt][jg * 2],     Q[mt], K[jg][0], K[jg][1]);
                mma16816h(S[mt][jg * 2 + 1], Q[mt], K[jg][2], K[jg][3]);
            }
    }

    // ================= softmax =================
    float invA[4], invB[4];
    #pragma unroll
    for (int mt = 0; mt < 4; mt++) {
        float sA = 0.f, sB = 0.f;
        #pragma unroll
        for (int nt = 0; nt < 6; nt++) {
            S[mt][nt][0] = __expf(S[mt][nt][0]);
            S[mt][nt][1] = __expf(S[mt][nt][1]);
            S[mt][nt][2] = __expf(S[mt][nt][2]);
            S[mt][nt][3] = __expf(S[mt][nt][3]);
            sA += S[mt][nt][0] + S[mt][nt][1];
            sB += S[mt][nt][2] + S[mt][nt][3];
        }
        sA += __shfl_xor_sync(0xFFFFFFFFu, sA, 1);
        sA += __shfl_xor_sync(0xFFFFFFFFu, sA, 2);
        sB += __shfl_xor_sync(0xFFFFFFFFu, sB, 1);
        sB += __shfl_xor_sync(0xFFFFFFFFu, sB, 2);
        invA[mt] = 1.f / sA;
        invB[mt] = 1.f / sB;
    }

    // ================= PV: M=64 N=32 K=48 =================
    float O[4][4][4] = {};
    #pragma unroll
    for (int jg = 0; jg < 3; jg++) {
        uint32_t P[4][4];
        #pragma unroll
        for (int mt = 0; mt < 4; mt++) {
            P[mt][0] = h2pack(S[mt][2 * jg][0],     S[mt][2 * jg][1]);
            P[mt][1] = h2pack(S[mt][2 * jg][2],     S[mt][2 * jg][3]);
            P[mt][2] = h2pack(S[mt][2 * jg + 1][0], S[mt][2 * jg + 1][1]);
            P[mt][3] = h2pack(S[mt][2 * jg + 1][2], S[mt][2 * jg + 1][3]);
        }
        uint32_t V[2][4];
        const uint32_t vo = (uint32_t)((jg * 16 + (lane & 7) + ((lane >> 3) & 1) * 8) * ARS
                                       + (lane >> 4) * 16);
        #pragma unroll
        for (int dg = 0; dg < 2; dg++)
            ldsm4t(V[dg], vc + vo + dg * 32);
        #pragma unroll
        for (int mt = 0; mt < 4; mt++)
            #pragma unroll
            for (int dg = 0; dg < 2; dg++) {
                mma16816h(O[mt][dg * 2],     P[mt], V[dg][0], V[dg][1]);
                mma16816h(O[mt][dg * 2 + 1], P[mt], V[dg][2], V[dg][3]);
            }
    }

    // ================= normalize + out via smem restage (144B rows) =================
    __syncwarp();
    #pragma unroll
    for (int mt = 0; mt < 4; mt++)
        #pragma unroll
        for (int nt = 0; nt < 4; nt++) {
            const int cc = nt * 8 + c2;
            *(float2*)(wbp + (mt * 16 + r) * 144 + cc * 4) =
                make_float2(O[mt][nt][0] * invA[mt], O[mt][nt][1] * invA[mt]);
            *(float2*)(wbp + (mt * 16 + r + 8) * 144 + cc * 4) =
                make_float2(O[mt][nt][2] * invB[mt], O[mt][nt][3] * invB[mt]);
        }
    __syncwarp();
    #pragma unroll
    for (int rr = 0; rr < 2; rr++) {
        const int r2 = lane + rr * 32;
        float v[32];
        #pragma unroll
        for (int i = 0; i < 8; i++)
            *(float4*)(v + i * 4) = *(const float4*)(wbp + r2 * 144 + i * 16);
        uint32_t hw[16];
        #pragma unroll
        for (int i = 0; i < 16; i++)
            hw[i] = h2pack(v[2 * i], v[2 * i + 1]);
        const size_t off = ((size_t)(w * NW + r2)) * CDIM + h * HD;
        #pragma unroll
        for (int i = 0; i < 4; i++)
            *(uint4*)(g_ao + off + i * 8) = *(uint4*)(hw + i * 4);
    }
}

// =================================================================================
extern "C" void kernel_launch(void* const* d_in, const int* in_sizes, int n_in,
                              void* d_out, int out_size)
{
    (void)in_sizes; (void)n_in; (void)out_size;
    const float* x     = (const float*)d_in[0];
    const float* Wqkv  = (const float*)d_in[1];
    const float* bqkv  = (const float*)d_in[2];
    const float* E_k   = (const float*)d_in[3];
    const float* E_v   = (const float*)d_in[4];
    const float* kbank = (const float*)d_in[5];
    const float* vbank = (const float*)d_in[6];
    const float* Wp    = (const float*)d_in[7];
    const float* bp    = (const float*)d_in[8];
    float* out = (float*)d_out;

    cudaFuncSetAttribute(hmma_gemm<0>,
                         cudaFuncAttributeMaxDynamicSharedMemorySize, SMEMB);
    cudaFuncSetAttribute(hmma_gemm<1>,
                         cudaFuncAttributeMaxDynamicSharedMemorySize, SMEMB);
    cudaFuncSetAttribute(attn_kernel,
                         cudaFuncAttributeMaxDynamicSharedMemorySize, ATTN_SM);

    conv_w<<<1040, 64>>>(Wqkv, Wp, E_k, E_v);
    hmma_gemm<0><<<dim3(6, 512), 256, SMEMB>>>(x, bqkv, nullptr);
    attn_kernel<<<BW * 4, 64, ATTN_SM>>>(kbank, vbank);
    hmma_gemm<1><<<dim3(2, 512), 256, SMEMB>>>(nullptr, bp, out);
}